// round 8
// baseline (speedup 1.0000x reference)
#include <cuda_runtime.h>

// CTPN loss: H=512, W=1024, K=10, N_POS=N_NEG=64.
// 64 threads / 2 warps; thread t owns pos anchor t AND neg anchor t.
// All loads independent & front-issued (128 gather chains). Merged cls
// accumulator, cnt via ballot+popc, 3-accumulator shuffle reduction,
// single barrier, STG.128 output.
// Output: 4 f32 = (loss, avg_loss_cls, avg_loss_reg_v, avg_loss_reg_o)

#define HW_ (512u * 1024u)
#define W_  1024u

__device__ __forceinline__ float smooth_l1(float d) {
    float a = fabsf(d);
    return (a < 1.0f) ? 0.5f * a * a : a - 0.5f;
}

// -log_softmax over 2 logits with d = s_other - s_target:
//   = relu(d) + log(1 + exp(-|d|))
__device__ __forceinline__ float ce_term(float d) {
    return fmaxf(d, 0.0f) + __logf(1.0f + __expf(-fabsf(d)));
}

__global__ void __launch_bounds__(64, 1) ctpn_loss_kernel(
    const float* __restrict__ scores,
    const float* __restrict__ vcoords,
    const float* __restrict__ sides,
    const int* __restrict__ pos_y, const int* __restrict__ pos_x, const int* __restrict__ pos_z,
    const int* __restrict__ neg_y, const int* __restrict__ neg_x, const int* __restrict__ neg_z,
    const float* __restrict__ v_targets,
    const int* __restrict__ side_mask,
    const float* __restrict__ side_targets,
    float* __restrict__ out, int out_size)
{
    const int tid = threadIdx.x;        // 0..63
    const int wid = tid >> 5;           // 0..1

    __shared__ float4 part[2];          // (cls, vsum, osum, cnt) per warp

    // ---- indices (6 independent loads) ----
    const int py = __ldg(pos_y + tid);
    const int px = __ldg(pos_x + tid);
    const int pz = __ldg(pos_z + tid);
    const int ny = __ldg(neg_y + tid);
    const int nx = __ldg(neg_x + tid);
    const int nz = __ldg(neg_z + tid);

    const unsigned pbase = (unsigned)(2 * pz) * HW_ + (unsigned)py * W_ + (unsigned)px;
    const unsigned sbase = (unsigned)pz * HW_ + (unsigned)py * W_ + (unsigned)px;
    const unsigned nbase = (unsigned)(2 * nz) * HW_ + (unsigned)ny * W_ + (unsigned)nx;

    // ---- all gathers + targets, independent, front-issued ----
    const float ps0 = __ldg(scores  + pbase);
    const float ps1 = __ldg(scores  + pbase + HW_);
    const float ns0 = __ldg(scores  + nbase);
    const float ns1 = __ldg(scores  + nbase + HW_);
    const float v0  = __ldg(vcoords + pbase);
    const float v1  = __ldg(vcoords + pbase + HW_);
    const float sp  = __ldg(sides   + sbase);
    const float2 vt = __ldg((const float2*)v_targets + tid);
    const int   mi  = __ldg(side_mask + tid);
    const float st  = __ldg(side_targets + tid);

    // ---- per-thread terms ----
    float cls  = ce_term(ps0 - ps1)      // pos, target=1
               + ce_term(ns1 - ns0);     // neg, target=0
    float vsum = smooth_l1(v0 - vt.x) + smooth_l1(v1 - vt.y);
    const float mm = (float)mi;
    float osum = smooth_l1(sp - st) * mm;

    // mask count: 0/1 mask -> ballot + popc (no float reduction needed)
    const unsigned bal = __ballot_sync(0xFFFFFFFFu, mi != 0);
    const float cnt = (float)__popc(bal);   // warp-uniform

    // ---- warp butterfly, 3 accumulators ----
    #pragma unroll
    for (int off = 16; off > 0; off >>= 1) {
        cls  += __shfl_xor_sync(0xFFFFFFFFu, cls,  off);
        vsum += __shfl_xor_sync(0xFFFFFFFFu, vsum, off);
        osum += __shfl_xor_sync(0xFFFFFFFFu, osum, off);
    }

    if ((tid & 31) == 0)
        part[wid] = make_float4(cls, vsum, osum, cnt);
    __syncthreads();

    if (tid == 0) {
        const float a = part[0].x + part[1].x;   // sum of 128 CE terms
        const float b = part[0].y + part[1].y;   // sum of 128 smoothL1 v terms
        const float c = part[0].z + part[1].z;   // masked side sum
        const float d = part[0].w + part[1].w;   // mask count

        const float avg_cls = a * (1.0f / 128.0f);
        const float avg_v   = b * (1.0f / 128.0f);
        const float avg_o   = (d > 0.0f) ? __fdividef(c, d) : 0.0f;
        const float loss    = avg_cls + avg_v + 2.0f * avg_o;

        if (out_size >= 4) {
            *(float4*)out = make_float4(loss, avg_cls, avg_v, avg_o);
        } else {
            if (out_size > 0) out[0] = loss;
            if (out_size > 1) out[1] = avg_cls;
            if (out_size > 2) out[2] = avg_v;
            if (out_size > 3) out[3] = avg_o;
        }
    }
}

extern "C" void kernel_launch(void* const* d_in, const int* in_sizes, int n_in,
                              void* d_out, int out_size) {
    const float* scores       = (const float*)d_in[0];
    const float* vcoords      = (const float*)d_in[1];
    const float* sides        = (const float*)d_in[2];
    const int*   pos_y        = (const int*)d_in[3];
    const int*   pos_x        = (const int*)d_in[4];
    const int*   pos_z        = (const int*)d_in[5];
    const int*   neg_y        = (const int*)d_in[6];
    const int*   neg_x        = (const int*)d_in[7];
    const int*   neg_z        = (const int*)d_in[8];
    const float* v_targets    = (const float*)d_in[9];
    const int*   side_mask    = (const int*)d_in[10];
    const float* side_targets = (const float*)d_in[11];

    ctpn_loss_kernel<<<1, 64>>>(scores, vcoords, sides,
                                pos_y, pos_x, pos_z,
                                neg_y, neg_x, neg_z,
                                v_targets, side_mask, side_targets,
                                (float*)d_out, out_size);
}

// round 9
// speedup vs baseline: 1.0435x; 1.0435x over previous
#include <cuda_runtime.h>

// CTPN loss: H=512, W=1024, K=10, N_POS=N_NEG=64.
// 64 threads / 2 warps; thread t owns pos anchor t AND neg anchor t.
// All 10 gathers/targets independent & front-issued (128 gather chains).
// Merged cls accumulator, cnt via ballot+popc, 3-accumulator butterfly,
// warp1-only smem partial, single barrier, STG.128 output.
// Output: 4 f32 = (loss, avg_loss_cls, avg_loss_reg_v, avg_loss_reg_o)

#define HW_ (512u * 1024u)
#define W_  1024u

__device__ __forceinline__ float smooth_l1(float d) {
    float a = fabsf(d);
    return (a < 1.0f) ? 0.5f * a * a : a - 0.5f;
}

// -log_softmax over 2 logits with d = s_other - s_target:
//   = relu(d) + log(1 + exp(-|d|))
__device__ __forceinline__ float ce_term(float d) {
    return fmaxf(d, 0.0f) + __logf(1.0f + __expf(-fabsf(d)));
}

__global__ void __launch_bounds__(64, 1) ctpn_loss_kernel(
    const float* __restrict__ scores,
    const float* __restrict__ vcoords,
    const float* __restrict__ sides,
    const int* __restrict__ pos_y, const int* __restrict__ pos_x, const int* __restrict__ pos_z,
    const int* __restrict__ neg_y, const int* __restrict__ neg_x, const int* __restrict__ neg_z,
    const float* __restrict__ v_targets,
    const int* __restrict__ side_mask,
    const float* __restrict__ side_targets,
    float* __restrict__ out, int out_size)
{
    const int tid = threadIdx.x;        // 0..63

    __shared__ float4 part1;            // warp 1 partial: (cls, vsum, osum, cnt)

    // ---- indices (6 independent loads) ----
    const int py = __ldg(pos_y + tid);
    const int px = __ldg(pos_x + tid);
    const int pz = __ldg(pos_z + tid);
    const int ny = __ldg(neg_y + tid);
    const int nx = __ldg(neg_x + tid);
    const int nz = __ldg(neg_z + tid);

    const unsigned pbase = (unsigned)(2 * pz) * HW_ + (unsigned)py * W_ + (unsigned)px;
    const unsigned sbase = (unsigned)pz * HW_ + (unsigned)py * W_ + (unsigned)px;
    const unsigned nbase = (unsigned)(2 * nz) * HW_ + (unsigned)ny * W_ + (unsigned)nx;

    // ---- all gathers + targets, independent, front-issued ----
    const float ps0 = __ldg(scores  + pbase);
    const float ps1 = __ldg(scores  + pbase + HW_);
    const float ns0 = __ldg(scores  + nbase);
    const float ns1 = __ldg(scores  + nbase + HW_);
    const float v0  = __ldg(vcoords + pbase);
    const float v1  = __ldg(vcoords + pbase + HW_);
    const float sp  = __ldg(sides   + sbase);
    const float2 vt = __ldg((const float2*)v_targets + tid);
    const int   mi  = __ldg(side_mask + tid);
    const float st  = __ldg(side_targets + tid);

    // ---- per-thread terms ----
    float cls  = ce_term(ps0 - ps1)      // pos, target=1
               + ce_term(ns1 - ns0);     // neg, target=0
    float vsum = smooth_l1(v0 - vt.x) + smooth_l1(v1 - vt.y);
    const float mm = (float)mi;
    float osum = smooth_l1(sp - st) * mm;

    // mask count: 0/1 mask -> ballot + popc (warp-uniform, no float reduction)
    const unsigned bal = __ballot_sync(0xFFFFFFFFu, mi != 0);
    const float cnt = (float)__popc(bal);

    // ---- warp butterfly, 3 accumulators ----
    #pragma unroll
    for (int off = 16; off > 0; off >>= 1) {
        cls  += __shfl_xor_sync(0xFFFFFFFFu, cls,  off);
        vsum += __shfl_xor_sync(0xFFFFFFFFu, vsum, off);
        osum += __shfl_xor_sync(0xFFFFFFFFu, osum, off);
    }

    // warp 1 publishes its partial; warp 0 keeps its own in registers
    if (tid == 32)
        part1 = make_float4(cls, vsum, osum, cnt);
    __syncthreads();

    if (tid == 0) {
        const float a = cls  + part1.x;          // sum of 128 CE terms
        const float b = vsum + part1.y;          // sum of 128 smoothL1 v terms
        const float c = osum + part1.z;          // masked side sum
        const float d = cnt  + part1.w;          // mask count

        const float avg_cls = a * (1.0f / 128.0f);
        const float avg_v   = b * (1.0f / 128.0f);
        const float avg_o   = (d > 0.0f) ? __fdividef(c, d) : 0.0f;
        const float loss    = avg_cls + avg_v + 2.0f * avg_o;

        if (out_size >= 4) {
            *(float4*)out = make_float4(loss, avg_cls, avg_v, avg_o);
        } else {
            if (out_size > 0) out[0] = loss;
            if (out_size > 1) out[1] = avg_cls;
            if (out_size > 2) out[2] = avg_v;
            if (out_size > 3) out[3] = avg_o;
        }
    }
}

extern "C" void kernel_launch(void* const* d_in, const int* in_sizes, int n_in,
                              void* d_out, int out_size) {
    const float* scores       = (const float*)d_in[0];
    const float* vcoords      = (const float*)d_in[1];
    const float* sides        = (const float*)d_in[2];
    const int*   pos_y        = (const int*)d_in[3];
    const int*   pos_x        = (const int*)d_in[4];
    const int*   pos_z        = (const int*)d_in[5];
    const int*   neg_y        = (const int*)d_in[6];
    const int*   neg_x        = (const int*)d_in[7];
    const int*   neg_z        = (const int*)d_in[8];
    const float* v_targets    = (const float*)d_in[9];
    const int*   side_mask    = (const int*)d_in[10];
    const float* side_targets = (const float*)d_in[11];

    ctpn_loss_kernel<<<1, 64>>>(scores, vcoords, sides,
                                pos_y, pos_x, pos_z,
                                neg_y, neg_x, neg_z,
                                v_targets, side_mask, side_targets,
                                (float*)d_out, out_size);
}